// round 1
// baseline (speedup 1.0000x reference)
#include <cuda_runtime.h>

// Problem constants (capacities for static scratch; runtime sizes used in loops)
#define NNODES 150000
#define MAXE   2000000
#define EMB4   32          // 128 floats = 32 float4 per node row
#define SCANB  1024        // scan block size

// ---------------- static device scratch (sanctioned workaround) -------------
__device__ float4 g_h0[NNODES * EMB4];   // layer 0 (= feats)
__device__ float4 g_h1[NNODES * EMB4];   // layer 1
__device__ float4 g_h2[NNODES * EMB4];   // layer 2
__device__ float4 g_h3[NNODES * EMB4];   // layer 3
__device__ int    g_cnt[NNODES];         // per-row degree histogram
__device__ int    g_rowptr[NNODES + 1];  // CSR row pointers
__device__ int    g_cursor[NNODES];      // counting-sort cursors
__device__ int    g_cols[MAXE];          // CSR column indices
__device__ float  g_vals[MAXE];          // CSR values
__device__ int    g_partials[512];       // scan block partials

__device__ __forceinline__ const float4* layer_buf(int i) {
    return (i == 0) ? g_h0 : (i == 1) ? g_h1 : (i == 2) ? g_h2 : g_h3;
}

// ---------------- CSR build ------------------------------------------------

__global__ void k_zero_cnt(int n) {
    int i = blockIdx.x * blockDim.x + threadIdx.x;
    if (i < n) g_cnt[i] = 0;
}

__global__ void k_hist(const int* __restrict__ row, int e) {
    int i = blockIdx.x * blockDim.x + threadIdx.x;
    if (i < e) atomicAdd(&g_cnt[row[i]], 1);
}

// per-block sums of g_cnt into g_partials
__global__ void k_block_sums(int n) {
    __shared__ int sh[SCANB];
    int gid = blockIdx.x * SCANB + threadIdx.x;
    sh[threadIdx.x] = (gid < n) ? g_cnt[gid] : 0;
    __syncthreads();
    for (int off = SCANB / 2; off > 0; off >>= 1) {
        if (threadIdx.x < off) sh[threadIdx.x] += sh[threadIdx.x + off];
        __syncthreads();
    }
    if (threadIdx.x == 0) g_partials[blockIdx.x] = sh[0];
}

// exclusive scan of block partials (nb <= 256), also writes g_rowptr[n] = total
__global__ void k_scan_partials(int nb, int n) {
    __shared__ int sh[257];
    int v = (threadIdx.x < nb) ? g_partials[threadIdx.x] : 0;
    sh[threadIdx.x] = v;
    __syncthreads();
    if (threadIdx.x == 0) {
        int run = 0;
        for (int i = 0; i < nb; i++) { int t = sh[i]; sh[i] = run; run += t; }
        g_rowptr[n] = run;
    }
    __syncthreads();
    if (threadIdx.x < nb) g_partials[threadIdx.x] = sh[threadIdx.x];
}

// per-block exclusive scan + partial offset -> g_rowptr, g_cursor
__global__ void k_scan_final(int n) {
    __shared__ int sh[SCANB];
    int gid = blockIdx.x * SCANB + threadIdx.x;
    int v = (gid < n) ? g_cnt[gid] : 0;
    sh[threadIdx.x] = v;
    __syncthreads();
    // Hillis-Steele inclusive scan
    for (int off = 1; off < SCANB; off <<= 1) {
        int t = (threadIdx.x >= off) ? sh[threadIdx.x - off] : 0;
        __syncthreads();
        sh[threadIdx.x] += t;
        __syncthreads();
    }
    if (gid < n) {
        int excl = sh[threadIdx.x] - v + g_partials[blockIdx.x];
        g_rowptr[gid] = excl;
        g_cursor[gid] = excl;
    }
}

// counting-sort edges into CSR slots
__global__ void k_fill(const int* __restrict__ row, const int* __restrict__ col,
                       const float* __restrict__ val, int e) {
    int i = blockIdx.x * blockDim.x + threadIdx.x;
    if (i < e) {
        int r = row[i];
        int p = atomicAdd(&g_cursor[r], 1);
        g_cols[p] = col[i];
        g_vals[p] = val[i];
    }
}

// ---------------- embeddings -----------------------------------------------

// h0 = concat(uEmbd, iEmbd), vectorized as float4
__global__ void k_init_h0(const float4* __restrict__ uE, const float4* __restrict__ iE,
                          int userNum, int n) {
    int i = blockIdx.x * blockDim.x + threadIdx.x;
    int total = n * EMB4;
    if (i < total) {
        int node = i >> 5;
        g_h0[i] = (node < userNum) ? uE[i] : iE[i - userNum * EMB4];
    }
}

// warp-per-row SpMM gather: hout[r] = sum_{e in row r} val[e] * hin[col[e]]
__global__ void k_spmm(int stage, int n) {
    const float4* __restrict__ hin = layer_buf(stage);
    float4* hout = const_cast<float4*>(layer_buf(stage + 1));

    int w    = (blockIdx.x * blockDim.x + threadIdx.x) >> 5;
    int lane = threadIdx.x & 31;
    if (w >= n) return;

    int s = g_rowptr[w];
    int e = g_rowptr[w + 1];

    float4 acc = make_float4(0.f, 0.f, 0.f, 0.f);
    for (int base = s; base < e; base += 32) {
        int idx = base + lane;
        int c = 0;
        float v = 0.f;
        if (idx < e) { c = g_cols[idx]; v = g_vals[idx]; }
        int m = min(32, e - base);
        #pragma unroll 4
        for (int j = 0; j < m; j++) {
            int   cj = __shfl_sync(0xffffffffu, c, j);
            float vj = __shfl_sync(0xffffffffu, v, j);
            float4 x = hin[cj * EMB4 + lane];
            acc.x = fmaf(vj, x.x, acc.x);
            acc.y = fmaf(vj, x.y, acc.y);
            acc.z = fmaf(vj, x.z, acc.z);
            acc.w = fmaf(vj, x.w, acc.w);
        }
    }
    hout[w * EMB4 + lane] = acc;
}

// warp-per-pair final dot of averaged layer sums
__global__ void k_dot(const int* __restrict__ uIdx, const int* __restrict__ vIdx,
                      int userNum, int B, float* __restrict__ out) {
    int w    = (blockIdx.x * blockDim.x + threadIdx.x) >> 5;
    int lane = threadIdx.x & 31;
    if (w >= B) return;

    int u = uIdx[w];
    int v = vIdx[w] + userNum;
    int ub = u * EMB4 + lane;
    int vb = v * EMB4 + lane;

    float4 a0 = g_h0[ub], a1 = g_h1[ub], a2 = g_h2[ub], a3 = g_h3[ub];
    float4 b0 = g_h0[vb], b1 = g_h1[vb], b2 = g_h2[vb], b3 = g_h3[vb];

    float sux = a0.x + a1.x + a2.x + a3.x, svx = b0.x + b1.x + b2.x + b3.x;
    float suy = a0.y + a1.y + a2.y + a3.y, svy = b0.y + b1.y + b2.y + b3.y;
    float suz = a0.z + a1.z + a2.z + a3.z, svz = b0.z + b1.z + b2.z + b3.z;
    float suw = a0.w + a1.w + a2.w + a3.w, svw = b0.w + b1.w + b2.w + b3.w;

    float d = sux * svx + suy * svy + suz * svz + suw * svw;
    #pragma unroll
    for (int off = 16; off > 0; off >>= 1)
        d += __shfl_xor_sync(0xffffffffu, d, off);

    if (lane == 0) out[w] = d * 0.0625f;   // (1/4)*(1/4) for the layer average
}

// ---------------- launch ----------------------------------------------------

extern "C" void kernel_launch(void* const* d_in, const int* in_sizes, int n_in,
                              void* d_out, int out_size) {
    const float4* uE   = (const float4*)d_in[0];
    const float4* iE   = (const float4*)d_in[1];
    const float*  Lval = (const float*)d_in[2];
    const int*    Lrow = (const int*)d_in[3];
    const int*    Lcol = (const int*)d_in[4];
    const int*    uIdx = (const int*)d_in[5];
    const int*    vIdx = (const int*)d_in[6];
    float*        out  = (float*)d_out;

    int userNum = in_sizes[0] / 128;
    int itemNum = in_sizes[1] / 128;
    int n = userNum + itemNum;
    if (n > NNODES) n = NNODES;
    int e = in_sizes[2];
    if (e > MAXE) e = MAXE;
    int B = in_sizes[5];

    // CSR build
    k_zero_cnt<<<(n + 255) / 256, 256>>>(n);
    k_hist<<<(e + 255) / 256, 256>>>(Lrow, e);
    int nb = (n + SCANB - 1) / SCANB;
    k_block_sums<<<nb, SCANB>>>(n);
    k_scan_partials<<<1, 256>>>(nb, n);
    k_scan_final<<<nb, SCANB>>>(n);
    k_fill<<<(e + 255) / 256, 256>>>(Lrow, Lcol, Lval, e);

    // layer 0 init
    k_init_h0<<<(n * EMB4 + 255) / 256, 256>>>(uE, iE, userNum, n);

    // 3 SpMM layers (warp per row, 8 warps/block)
    int spmm_blocks = (n + 7) / 8;
    k_spmm<<<spmm_blocks, 256>>>(0, n);
    k_spmm<<<spmm_blocks, 256>>>(1, n);
    k_spmm<<<spmm_blocks, 256>>>(2, n);

    // final batched dot
    k_dot<<<(B + 7) / 8, 256>>>(uIdx, vIdx, userNum, B, out);
}